// round 12
// baseline (speedup 1.0000x reference)
#include <cuda_runtime.h>
#include <cuda_bf16.h>
#include <cstdint>

#define N_NODES   100000
#define N_EDGES   3200000
#define N_GRAPHS  256
#define FEAT      128
#define TPITCH    68    // fp32 smem pitch for 64-row A tile (16B aligned)

// ---------------- scratch ----------------
__device__ __align__(16) int   g_cnt[N_NODES];
__device__ __align__(16) int   g_fill[N_NODES];
__device__ __align__(16) int   g_rowstart[N_NODES];   // intra-block exclusive prefix
__device__ __align__(16) int   g_bsum[512];           // exclusive block sums
__device__ __align__(16) float g_dis[N_NODES];
__device__ __align__(16) int2  g_cv[N_EDGES];
__device__ __align__(16) __nv_bfloat16 g_hb[(size_t)N_NODES * FEAT];  // GEMM out (bf16, gathered)
__device__ __align__(16) float g_a[(size_t)N_NODES * FEAT];           // agg out (fp32, post-relu)
__device__ int g_is64;

__device__ __forceinline__ int ld_idx(const int* __restrict__ p, long long i, int is64) {
    if (is64) return (int)(((const long long*)p)[i]);
    return p[i];
}

// ---------------- dtype sniff ----------------
__global__ void k_sniff(const int* __restrict__ ei) {
    if (threadIdx.x == 0 && blockIdx.x == 0) {
        int odd = 0;
        for (int i = 1; i < 128; i += 2) odd |= ei[i];
        g_is64 = (odd == 0) ? 1 : 0;
    }
}

// ---------------- prep ----------------
__global__ void k_zero(int n) {
    int i = blockIdx.x * blockDim.x + threadIdx.x;
    if (i < n) { g_cnt[i] = 0; g_fill[i] = 0; }
}
__global__ void k_count(const int* __restrict__ ei, int E, int n) {
    int e = blockIdx.x * blockDim.x + threadIdx.x;
    if (e >= E) return;
    int d = ld_idx(ei, (long long)E + e, g_is64);
    if ((unsigned)d < (unsigned)n) atomicAdd(&g_cnt[d], 1);
}
// scan1 + dis fused
__global__ void k_scan1(int n) {
    __shared__ int s[256];
    int t = threadIdx.x;
    int i = blockIdx.x * 256 + t;
    int v = (i < n) ? g_cnt[i] : 0;
    if (i < n) g_dis[i] = rsqrtf((float)v + 1.0f);
    s[t] = v; __syncthreads();
    for (int off = 1; off < 256; off <<= 1) {
        int a = (t >= off) ? s[t - off] : 0;
        __syncthreads();
        s[t] += a;
        __syncthreads();
    }
    if (i < n) g_rowstart[i] = s[t] - v;
    if (t == 255) g_bsum[blockIdx.x] = s[255];
}
__global__ void k_scan2(int nb) {
    __shared__ int s[512];
    int t = threadIdx.x;
    int v = (t < nb) ? g_bsum[t] : 0;
    s[t] = v; __syncthreads();
    for (int off = 1; off < 512; off <<= 1) {
        int a = (t >= off) ? s[t - off] : 0;
        __syncthreads();
        s[t] += a;
        __syncthreads();
    }
    if (t < nb) g_bsum[t] = s[t] - v;
}
// fillcsr with inlined scan3 (rowstart[d] + bsum[d>>8])
__global__ void k_fillcsr(const int* __restrict__ ei, int E, int n) {
    int e = blockIdx.x * blockDim.x + threadIdx.x;
    if (e >= E) return;
    int is64 = g_is64;
    int s = ld_idx(ei, e, is64);
    int d = ld_idx(ei, (long long)E + e, is64);
    if ((unsigned)s >= (unsigned)n || (unsigned)d >= (unsigned)n) return;
    int pos = atomicAdd(&g_fill[d], 1);
    int base = g_rowstart[d] + g_bsum[d >> 8];
    float v = g_dis[s] * g_dis[d];
    g_cv[base + pos] = make_int2(s, __float_as_int(v));
}

// ---------------- GEMM: g_hb[n,128] = A[n,128] @ W[128,128] ----------------
// 64x128 block tile, 256 threads (8 ty x 32 tx), thread tile 8m x 4n.
// Warp = one ty row-group -> A fragment is ONE smem address per warp (pure broadcast).
// FFMA2 accumulators, 8 chunks of K=16, double-buffered with register prefetch.
__global__ __launch_bounds__(256, 3) void k_gemmW(const float* __restrict__ Ain,
                                                  const float* __restrict__ W, int n) {
    __shared__ float As[2][16][TPITCH];   // [k][row] transposed, 64 rows
    __shared__ float Ws[2][16][128];
    const float* A = Ain ? Ain : g_a;
    int tid = threadIdx.x;
    int row0 = blockIdx.x << 6;           // 64-row tile
    int tx = tid & 31, ty = tid >> 5;
    int m0 = ty << 3, n0 = tx << 2;

    unsigned long long acc2[8][2];
#pragma unroll
    for (int i = 0; i < 8; i++) { acc2[i][0] = 0ull; acc2[i][1] = 0ull; }

    // staging: A chunk = 64 rows x 16 k = 256 float4 (1/thread),
    //          W chunk = 16 k x 128 n = 512 float4 (2/thread)
    int ar = tid >> 2, ak = (tid & 3) << 2;           // A: row, k-offset
    int iw0 = tid * 2, iw1 = tid * 2 + 1;
    int wk0 = iw0 >> 5, wc0 = (iw0 & 31) << 2;
    int wk1 = iw1 >> 5, wc1 = (iw1 & 31) << 2;

    float4 pa, pw0, pw1;
    pa  = (row0 + ar < n) ? *(const float4*)(A + (size_t)(row0 + ar) * FEAT + ak)
                          : make_float4(0.f, 0.f, 0.f, 0.f);
    pw0 = *(const float4*)(W + (size_t)wk0 * FEAT + wc0);
    pw1 = *(const float4*)(W + (size_t)wk1 * FEAT + wc1);

#pragma unroll 1
    for (int c = 0; c < 8; c++) {
        int b = c & 1;
        As[b][ak + 0][ar] = pa.x;
        As[b][ak + 1][ar] = pa.y;
        As[b][ak + 2][ar] = pa.z;
        As[b][ak + 3][ar] = pa.w;
        *(float4*)(&Ws[b][wk0][wc0]) = pw0;
        *(float4*)(&Ws[b][wk1][wc1]) = pw1;
        __syncthreads();

        if (c < 7) {
            int k0 = (c + 1) << 4;
            pa  = (row0 + ar < n) ? *(const float4*)(A + (size_t)(row0 + ar) * FEAT + k0 + ak)
                                  : make_float4(0.f, 0.f, 0.f, 0.f);
            pw0 = *(const float4*)(W + (size_t)(k0 + wk0) * FEAT + wc0);
            pw1 = *(const float4*)(W + (size_t)(k0 + wk1) * FEAT + wc1);
        }

#pragma unroll
        for (int k = 0; k < 16; k++) {
            // A: 2x LDS.128, single address per warp (broadcast)
            float4 a0 = *(float4*)(&As[b][k][m0]);
            float4 a1 = *(float4*)(&As[b][k][m0 + 4]);
            // W: 1x LDS.128 (per-lane distinct)
            ulonglong2 wq = *(ulonglong2*)(&Ws[b][k][n0]);
            unsigned long long wp0 = wq.x, wp1 = wq.y;
            float av[8] = {a0.x, a0.y, a0.z, a0.w, a1.x, a1.y, a1.z, a1.w};
#pragma unroll
            for (int i = 0; i < 8; i++) {
                unsigned long long ap;
                asm("mov.b64 %0, {%1, %1};" : "=l"(ap) : "f"(av[i]));
                asm("fma.rn.f32x2 %0, %1, %2, %0;" : "+l"(acc2[i][0]) : "l"(ap), "l"(wp0));
                asm("fma.rn.f32x2 %0, %1, %2, %0;" : "+l"(acc2[i][1]) : "l"(ap), "l"(wp1));
            }
        }
        __syncthreads();
    }

#pragma unroll
    for (int i = 0; i < 8; i++) {
        int r = row0 + m0 + i;
        if (r < n) {
            uint32_t lo0, hi0, lo1, hi1;
            asm("mov.b64 {%0, %1}, %2;" : "=r"(lo0), "=r"(hi0) : "l"(acc2[i][0]));
            asm("mov.b64 {%0, %1}, %2;" : "=r"(lo1), "=r"(hi1) : "l"(acc2[i][1]));
            __nv_bfloat162 p0 = __floats2bfloat162_rn(__uint_as_float(lo0), __uint_as_float(hi0));
            __nv_bfloat162 p1 = __floats2bfloat162_rn(__uint_as_float(lo1), __uint_as_float(hi1));
            uint2 st;
            st.x = *(uint32_t*)&p0;
            st.y = *(uint32_t*)&p1;
            *(uint2*)(g_hb + (size_t)r * FEAT + n0) = st;
        }
    }
}

// ---------------- aggregation: g_a[i] = relu(b + dis^2*hb[i] + sum val*hb[col]) ----------------
__global__ void k_agg(const float* __restrict__ bias, int n) {
    int w = (blockIdx.x * blockDim.x + threadIdx.x) >> 5;
    int lane = threadIdx.x & 31;
    if (w >= n) return;
    int start = g_rowstart[w] + g_bsum[w >> 8];
    int m = g_cnt[w];
    float d = g_dis[w];
    float dd = d * d;

    uint2 sv = *((const uint2*)(g_hb + (size_t)w * FEAT) + lane);
    float2 s0 = __bfloat1622float2(*(const __nv_bfloat162*)&sv.x);
    float2 s1 = __bfloat1622float2(*(const __nv_bfloat162*)&sv.y);
    float4 bv = __ldg((const float4*)bias + lane);
    float4 acc;
    acc.x = bv.x + s0.x * dd;
    acc.y = bv.y + s0.y * dd;
    acc.z = bv.z + s1.x * dd;
    acc.w = bv.w + s1.y * dd;

    for (int j = 0; j < m; j++) {
        int2 cv = g_cv[start + j];
        float v = __int_as_float(cv.y);
        uint2 hm = *((const uint2*)(g_hb + (size_t)cv.x * FEAT) + lane);
        float2 f0 = __bfloat1622float2(*(const __nv_bfloat162*)&hm.x);
        float2 f1 = __bfloat1622float2(*(const __nv_bfloat162*)&hm.y);
        acc.x = fmaf(f0.x, v, acc.x);
        acc.y = fmaf(f0.y, v, acc.y);
        acc.z = fmaf(f1.x, v, acc.z);
        acc.w = fmaf(f1.y, v, acc.w);
    }
    acc.x = fmaxf(acc.x, 0.f);
    acc.y = fmaxf(acc.y, 0.f);
    acc.z = fmaxf(acc.z, 0.f);
    acc.w = fmaxf(acc.w, 0.f);
    ((float4*)(g_a + (size_t)w * FEAT))[lane] = acc;
}

// ---------------- fused mean-pool + MLP head ----------------
__global__ void k_poolmlp(const int* __restrict__ batch, int n,
                          const float* __restrict__ w1, const float* __restrict__ b1,
                          const float* __restrict__ w2, const float* __restrict__ b2,
                          float* __restrict__ out) {
    int g = blockIdx.x;
    int t = threadIdx.x;  // 128
    int is64 = g_is64;
    __shared__ float gs[128];
    __shared__ float ts[128];

    int lo = 0, hi = n;
    while (lo < hi) { int mid = (lo + hi) >> 1; if (ld_idx(batch, mid, is64) < g) lo = mid + 1; else hi = mid; }
    int s = lo;
    hi = n;
    while (lo < hi) { int mid = (lo + hi) >> 1; if (ld_idx(batch, mid, is64) <= g) lo = mid + 1; else hi = mid; }
    int e = lo;
    float acc = 0.f;
    for (int i = s; i < e; i++) acc += g_a[(size_t)i * FEAT + t];
    int c = e - s;
    gs[t] = acc / (float)(c > 0 ? c : 1);
    __syncthreads();

    float h = b1[t];
#pragma unroll 8
    for (int k = 0; k < 128; k++) h = fmaf(gs[k], w1[k * 128 + t], h);
    ts[t] = fmaxf(h, 0.f);
    __syncthreads();
    if (t < 10) {
        float o = b2[t];
#pragma unroll 8
        for (int j = 0; j < 128; j++) o = fmaf(ts[j], w2[j * 10 + t], o);
        out[g * 10 + t] = o;
    }
}

// ---------------- launcher ----------------
extern "C" void kernel_launch(void* const* d_in, const int* in_sizes, int n_in,
                              void* d_out, int out_size) {
    const float* x     = (const float*)d_in[0];
    const int*   ei    = (const int*)d_in[1];
    const int*   batch = (const int*)d_in[2];
    const float* W1 = (const float*)d_in[3];  const float* b1 = (const float*)d_in[4];
    const float* W2 = (const float*)d_in[5];  const float* b2 = (const float*)d_in[6];
    const float* W3 = (const float*)d_in[7];  const float* b3 = (const float*)d_in[8];
    const float* l1w = (const float*)d_in[9];  const float* l1b = (const float*)d_in[10];
    const float* l2w = (const float*)d_in[11]; const float* l2b = (const float*)d_in[12];
    float* out = (float*)d_out;

    int n = in_sizes[0] / FEAT;   // 100000
    int E = in_sizes[1] / 2;      // 3200000

    int nb = (n + 255) / 256;
    int eb = (E + 255) / 256;
    int gb = (n + 63) / 64;       // 64-row tiles
    long long athreads = (long long)n * 32;
    int ab = (int)((athreads + 255) / 256);

    // order keeps gemm1 as my 4th launch (ncu -s 5 profiles it)
    k_sniff  <<<1, 32>>>(ei);
    k_zero   <<<nb, 256>>>(n);
    k_count  <<<eb, 256>>>(ei, E, n);
    k_gemmW  <<<gb, 256>>>(x, W1, n);       // layer-1 GEMM (independent of CSR prep)
    k_scan1  <<<nb, 256>>>(n);
    k_scan2  <<<1, 512>>>(nb);
    k_fillcsr<<<eb, 256>>>(ei, E, n);

    k_agg  <<<ab, 256>>>(b1, n);
    k_gemmW<<<gb, 256>>>(nullptr, W2, n);
    k_agg  <<<ab, 256>>>(b2, n);
    k_gemmW<<<gb, 256>>>(nullptr, W3, n);
    k_agg  <<<ab, 256>>>(b3, n);

    k_poolmlp<<<N_GRAPHS, 128>>>(batch, n, l1w, l1b, l2w, l2b, out);
}

// round 13
// speedup vs baseline: 1.4888x; 1.4888x over previous
#include <cuda_runtime.h>
#include <cuda_bf16.h>
#include <cstdint>

#define N_NODES   100000
#define N_EDGES   3200000
#define N_GRAPHS  256
#define FEAT      128
#define APITCH    132   // fp32 smem pitch (16B-aligned float4 rows)

// ---------------- scratch ----------------
__device__ __align__(16) int   g_cnt[N_NODES];
__device__ __align__(16) int   g_fill[N_NODES];
__device__ __align__(16) int   g_rowstart[N_NODES];   // intra-block exclusive prefix
__device__ __align__(16) int   g_bsum[512];           // exclusive block sums
__device__ __align__(16) float g_dis[N_NODES];
__device__ __align__(16) int2  g_cv[N_EDGES];
__device__ __align__(16) __nv_bfloat16 g_hb[(size_t)N_NODES * FEAT];  // GEMM out (bf16, gathered)
__device__ __align__(16) float g_a[(size_t)N_NODES * FEAT];           // agg out (fp32, post-relu)
__device__ int g_is64;

__device__ __forceinline__ int ld_idx(const int* __restrict__ p, long long i, int is64) {
    if (is64) return (int)(((const long long*)p)[i]);
    return p[i];
}

// ---------------- dtype sniff ----------------
__global__ void k_sniff(const int* __restrict__ ei) {
    if (threadIdx.x == 0 && blockIdx.x == 0) {
        int odd = 0;
        for (int i = 1; i < 128; i += 2) odd |= ei[i];
        g_is64 = (odd == 0) ? 1 : 0;
    }
}

// ---------------- prep ----------------
__global__ void k_zero(int n) {
    int i = blockIdx.x * blockDim.x + threadIdx.x;
    if (i < n) { g_cnt[i] = 0; g_fill[i] = 0; }
}
__global__ void k_count(const int* __restrict__ ei, int E, int n) {
    int e = blockIdx.x * blockDim.x + threadIdx.x;
    if (e >= E) return;
    int d = ld_idx(ei, (long long)E + e, g_is64);
    if ((unsigned)d < (unsigned)n) atomicAdd(&g_cnt[d], 1);
}
// scan1 + dis fused
__global__ void k_scan1(int n) {
    __shared__ int s[256];
    int t = threadIdx.x;
    int i = blockIdx.x * 256 + t;
    int v = (i < n) ? g_cnt[i] : 0;
    if (i < n) g_dis[i] = rsqrtf((float)v + 1.0f);
    s[t] = v; __syncthreads();
    for (int off = 1; off < 256; off <<= 1) {
        int a = (t >= off) ? s[t - off] : 0;
        __syncthreads();
        s[t] += a;
        __syncthreads();
    }
    if (i < n) g_rowstart[i] = s[t] - v;
    if (t == 255) g_bsum[blockIdx.x] = s[255];
}
__global__ void k_scan2(int nb) {
    __shared__ int s[512];
    int t = threadIdx.x;
    int v = (t < nb) ? g_bsum[t] : 0;
    s[t] = v; __syncthreads();
    for (int off = 1; off < 512; off <<= 1) {
        int a = (t >= off) ? s[t - off] : 0;
        __syncthreads();
        s[t] += a;
        __syncthreads();
    }
    if (t < nb) g_bsum[t] = s[t] - v;
}
// fillcsr with inlined scan3 (rowstart[d] + bsum[d>>8])
__global__ void k_fillcsr(const int* __restrict__ ei, int E, int n) {
    int e = blockIdx.x * blockDim.x + threadIdx.x;
    if (e >= E) return;
    int is64 = g_is64;
    int s = ld_idx(ei, e, is64);
    int d = ld_idx(ei, (long long)E + e, is64);
    if ((unsigned)s >= (unsigned)n || (unsigned)d >= (unsigned)n) return;
    int pos = atomicAdd(&g_fill[d], 1);
    int base = g_rowstart[d] + g_bsum[d >> 8];
    float v = g_dis[s] * g_dis[d];
    g_cv[base + pos] = make_int2(s, __float_as_int(v));
}

// ---------------- GEMM: g_hb[n,128] = A[n,128] @ W[128,128] (R11 config) ----------------
// 128x128 block tile, 16x16 threads, 8x8 register tile, FFMA2 accumulators,
// 8 chunks of K=16, 2-stage smem double-buffer with register prefetch.
__global__ __launch_bounds__(256) void k_gemmW(const float* __restrict__ Ain,
                                               const float* __restrict__ W, int n) {
    __shared__ float As[2][16][APITCH];
    __shared__ float Ws[2][16][128];
    const float* A = Ain ? Ain : g_a;
    int tid = threadIdx.x;
    int row0 = blockIdx.x << 7;
    int tx = tid & 15, ty = tid >> 4;
    int m0 = ty << 3, n0 = tx << 3;

    unsigned long long acc2[8][4];
#pragma unroll
    for (int i = 0; i < 8; i++)
#pragma unroll
        for (int j = 0; j < 4; j++) acc2[i][j] = 0ull;

    int ia0 = tid * 2, ia1 = tid * 2 + 1;
    int ar0 = ia0 >> 2, ak0 = (ia0 & 3) << 2;
    int ar1 = ia1 >> 2, ak1 = (ia1 & 3) << 2;
    int wk0 = ia0 >> 5, wc0 = (ia0 & 31) << 2;
    int wk1 = ia1 >> 5, wc1 = (ia1 & 31) << 2;

    float4 pa0, pa1, pw0, pw1;
    pa0 = (row0 + ar0 < n) ? *(const float4*)(A + (size_t)(row0 + ar0) * FEAT + ak0)
                           : make_float4(0.f, 0.f, 0.f, 0.f);
    pa1 = (row0 + ar1 < n) ? *(const float4*)(A + (size_t)(row0 + ar1) * FEAT + ak1)
                           : make_float4(0.f, 0.f, 0.f, 0.f);
    pw0 = *(const float4*)(W + (size_t)wk0 * FEAT + wc0);
    pw1 = *(const float4*)(W + (size_t)wk1 * FEAT + wc1);

#pragma unroll 1
    for (int c = 0; c < 8; c++) {
        int b = c & 1;
        As[b][ak0 + 0][ar0] = pa0.x;
        As[b][ak0 + 1][ar0] = pa0.y;
        As[b][ak0 + 2][ar0] = pa0.z;
        As[b][ak0 + 3][ar0] = pa0.w;
        As[b][ak1 + 0][ar1] = pa1.x;
        As[b][ak1 + 1][ar1] = pa1.y;
        As[b][ak1 + 2][ar1] = pa1.z;
        As[b][ak1 + 3][ar1] = pa1.w;
        *(float4*)(&Ws[b][wk0][wc0]) = pw0;
        *(float4*)(&Ws[b][wk1][wc1]) = pw1;
        __syncthreads();

        if (c < 7) {
            int k0 = (c + 1) << 4;
            pa0 = (row0 + ar0 < n) ? *(const float4*)(A + (size_t)(row0 + ar0) * FEAT + k0 + ak0)
                                   : make_float4(0.f, 0.f, 0.f, 0.f);
            pa1 = (row0 + ar1 < n) ? *(const float4*)(A + (size_t)(row0 + ar1) * FEAT + k0 + ak1)
                                   : make_float4(0.f, 0.f, 0.f, 0.f);
            pw0 = *(const float4*)(W + (size_t)(k0 + wk0) * FEAT + wc0);
            pw1 = *(const float4*)(W + (size_t)(k0 + wk1) * FEAT + wc1);
        }

#pragma unroll
        for (int k = 0; k < 16; k++) {
            float4 a0 = *(float4*)(&As[b][k][m0]);
            float4 a1 = *(float4*)(&As[b][k][m0 + 4]);
            float av[8] = {a0.x, a0.y, a0.z, a0.w, a1.x, a1.y, a1.z, a1.w};
            ulonglong2 bq0 = *(ulonglong2*)(&Ws[b][k][n0]);
            ulonglong2 bq1 = *(ulonglong2*)(&Ws[b][k][n0 + 4]);
            unsigned long long bp0 = bq0.x, bp1 = bq0.y, bp2 = bq1.x, bp3 = bq1.y;
#pragma unroll
            for (int i = 0; i < 8; i++) {
                unsigned long long ap;
                asm("mov.b64 %0, {%1, %1};" : "=l"(ap) : "f"(av[i]));
                asm("fma.rn.f32x2 %0, %1, %2, %0;" : "+l"(acc2[i][0]) : "l"(ap), "l"(bp0));
                asm("fma.rn.f32x2 %0, %1, %2, %0;" : "+l"(acc2[i][1]) : "l"(ap), "l"(bp1));
                asm("fma.rn.f32x2 %0, %1, %2, %0;" : "+l"(acc2[i][2]) : "l"(ap), "l"(bp2));
                asm("fma.rn.f32x2 %0, %1, %2, %0;" : "+l"(acc2[i][3]) : "l"(ap), "l"(bp3));
            }
        }
        __syncthreads();
    }

#pragma unroll
    for (int i = 0; i < 8; i++) {
        int r = row0 + m0 + i;
        if (r < n) {
            uint32_t o[4];
#pragma unroll
            for (int j = 0; j < 4; j++) {
                uint32_t lo, hi;
                asm("mov.b64 {%0, %1}, %2;" : "=r"(lo), "=r"(hi) : "l"(acc2[i][j]));
                __nv_bfloat162 p = __floats2bfloat162_rn(__uint_as_float(lo), __uint_as_float(hi));
                o[j] = *(uint32_t*)&p;
            }
            *(uint4*)(g_hb + (size_t)r * FEAT + n0) = make_uint4(o[0], o[1], o[2], o[3]);
        }
    }
}

// ---------------- aggregation: g_a[i] = relu(b + dis^2*hb[i] + sum val*hb[col]) ----------------
__global__ void k_agg(const float* __restrict__ bias, int n) {
    int w = (blockIdx.x * blockDim.x + threadIdx.x) >> 5;
    int lane = threadIdx.x & 31;
    if (w >= n) return;
    int start = g_rowstart[w] + g_bsum[w >> 8];
    int m = g_cnt[w];
    float d = g_dis[w];
    float dd = d * d;

    uint2 sv = *((const uint2*)(g_hb + (size_t)w * FEAT) + lane);
    float2 s0 = __bfloat1622float2(*(const __nv_bfloat162*)&sv.x);
    float2 s1 = __bfloat1622float2(*(const __nv_bfloat162*)&sv.y);
    float4 bv = __ldg((const float4*)bias + lane);
    float4 acc;
    acc.x = bv.x + s0.x * dd;
    acc.y = bv.y + s0.y * dd;
    acc.z = bv.z + s1.x * dd;
    acc.w = bv.w + s1.y * dd;

    for (int j = 0; j < m; j++) {
        int2 cv = g_cv[start + j];
        float v = __int_as_float(cv.y);
        uint2 hm = *((const uint2*)(g_hb + (size_t)cv.x * FEAT) + lane);
        float2 f0 = __bfloat1622float2(*(const __nv_bfloat162*)&hm.x);
        float2 f1 = __bfloat1622float2(*(const __nv_bfloat162*)&hm.y);
        acc.x = fmaf(f0.x, v, acc.x);
        acc.y = fmaf(f0.y, v, acc.y);
        acc.z = fmaf(f1.x, v, acc.z);
        acc.w = fmaf(f1.y, v, acc.w);
    }
    acc.x = fmaxf(acc.x, 0.f);
    acc.y = fmaxf(acc.y, 0.f);
    acc.z = fmaxf(acc.z, 0.f);
    acc.w = fmaxf(acc.w, 0.f);
    ((float4*)(g_a + (size_t)w * FEAT))[lane] = acc;
}

// ---------------- fused mean-pool + MLP head ----------------
__global__ void k_poolmlp(const int* __restrict__ batch, int n,
                          const float* __restrict__ w1, const float* __restrict__ b1,
                          const float* __restrict__ w2, const float* __restrict__ b2,
                          float* __restrict__ out) {
    int g = blockIdx.x;
    int t = threadIdx.x;  // 128
    int is64 = g_is64;
    __shared__ float gs[128];
    __shared__ float ts[128];

    int lo = 0, hi = n;
    while (lo < hi) { int mid = (lo + hi) >> 1; if (ld_idx(batch, mid, is64) < g) lo = mid + 1; else hi = mid; }
    int s = lo;
    hi = n;
    while (lo < hi) { int mid = (lo + hi) >> 1; if (ld_idx(batch, mid, is64) <= g) lo = mid + 1; else hi = mid; }
    int e = lo;
    float acc = 0.f;
    for (int i = s; i < e; i++) acc += g_a[(size_t)i * FEAT + t];
    int c = e - s;
    gs[t] = acc / (float)(c > 0 ? c : 1);
    __syncthreads();

    float h = b1[t];
#pragma unroll 8
    for (int k = 0; k < 128; k++) h = fmaf(gs[k], w1[k * 128 + t], h);
    ts[t] = fmaxf(h, 0.f);
    __syncthreads();
    if (t < 10) {
        float o = b2[t];
#pragma unroll 8
        for (int j = 0; j < 128; j++) o = fmaf(ts[j], w2[j * 10 + t], o);
        out[g * 10 + t] = o;
    }
}

// ---------------- launcher: layer-1 GEMM overlapped with CSR prep ----------------
extern "C" void kernel_launch(void* const* d_in, const int* in_sizes, int n_in,
                              void* d_out, int out_size) {
    const float* x     = (const float*)d_in[0];
    const int*   ei    = (const int*)d_in[1];
    const int*   batch = (const int*)d_in[2];
    const float* W1 = (const float*)d_in[3];  const float* b1 = (const float*)d_in[4];
    const float* W2 = (const float*)d_in[5];  const float* b2 = (const float*)d_in[6];
    const float* W3 = (const float*)d_in[7];  const float* b3 = (const float*)d_in[8];
    const float* l1w = (const float*)d_in[9];  const float* l1b = (const float*)d_in[10];
    const float* l2w = (const float*)d_in[11]; const float* l2b = (const float*)d_in[12];
    float* out = (float*)d_out;

    int n = in_sizes[0] / FEAT;   // 100000
    int E = in_sizes[1] / 2;      // 3200000

    int nb = (n + 255) / 256;
    int eb = (E + 255) / 256;
    int gb = (n + 127) / 128;
    long long athreads = (long long)n * 32;
    int ab = (int)((athreads + 255) / 256);

    static cudaStream_t s1;
    static cudaEvent_t evFork, evGemm;
    static int inited = 0;
    if (!inited) {
        cudaStreamCreateWithFlags(&s1, cudaStreamNonBlocking);
        cudaEventCreateWithFlags(&evFork, cudaEventDisableTiming);
        cudaEventCreateWithFlags(&evGemm, cudaEventDisableTiming);
        inited = 1;
    }

    // fork: layer-1 GEMM on s1, CSR prep on default stream, join before agg1
    cudaEventRecord(evFork, 0);
    cudaStreamWaitEvent(s1, evFork, 0);

    k_sniff  <<<1, 32>>>(ei);                 // launch 1
    k_zero   <<<nb, 256>>>(n);                // launch 2
    k_count  <<<eb, 256>>>(ei, E, n);         // launch 3
    k_gemmW  <<<gb, 256, 0, s1>>>(x, W1, n);  // launch 4 (profiled by ncu -s 5)
    k_scan1  <<<nb, 256>>>(n);
    k_scan2  <<<1, 512>>>(nb);
    k_fillcsr<<<eb, 256>>>(ei, E, n);

    cudaEventRecord(evGemm, s1);
    cudaStreamWaitEvent(0, evGemm, 0);

    k_agg  <<<ab, 256>>>(b1, n);
    k_gemmW<<<gb, 256>>>(nullptr, W2, n);
    k_agg  <<<ab, 256>>>(b2, n);
    k_gemmW<<<gb, 256>>>(nullptr, W3, n);
    k_agg  <<<ab, 256>>>(b3, n);

    k_poolmlp<<<N_GRAPHS, 128>>>(batch, n, l1w, l1b, l2w, l2b, out);
}